// round 1
// baseline (speedup 1.0000x reference)
#include <cuda_runtime.h>
#include <math.h>

#define EMBED 1024
#define NHEAD 16
#define HDIM  64
#define BB    2
#define SS    2048
#define MTOT  (BB*SS)   // 4096

// Scratch (allocation-free contract: __device__ globals)
__device__ float g_q [MTOT*EMBED];
__device__ float g_k [MTOT*EMBED];
__device__ float g_v [MTOT*EMBED];
__device__ float g_ao[MTOT*EMBED];

// ---------------------------------------------------------------------------
// GEMM (NT): C[M,N] = A[M,K] * B[N,K]^T (+ bias[n] if bias != nullptr)
// Tiles: BM=128, BN=128, BK=8; 256 threads; 8x8 micro-tile per thread.
// ---------------------------------------------------------------------------
__global__ void __launch_bounds__(256, 2)
gemm_nt_kernel(const float* __restrict__ A, const float* __restrict__ B,
               const float* __restrict__ bias, float* __restrict__ C,
               int M, int N, int K)
{
    __shared__ float As[8][128];
    __shared__ float Bs[8][128];

    const int tid = threadIdx.x;
    const int tx  = tid & 15;       // 0..15
    const int ty  = tid >> 4;       // 0..15
    const int m0  = blockIdx.y * 128;
    const int n0  = blockIdx.x * 128;

    // Loader mapping: each thread fetches one float4 (4 k's of one row) per tile.
    const int lr = tid >> 1;        // row 0..127
    const int lk = (tid & 1) * 4;   // k offset 0 or 4

    float acc[8][8];
#pragma unroll
    for (int i = 0; i < 8; i++)
#pragma unroll
        for (int j = 0; j < 8; j++) acc[i][j] = 0.f;

    const float* Aptr = A + (size_t)(m0 + lr) * K + lk;
    const float* Bptr = B + (size_t)(n0 + lr) * K + lk;

    for (int kt = 0; kt < K; kt += 8) {
        float4 av = *(const float4*)(Aptr + kt);
        float4 bv = *(const float4*)(Bptr + kt);
        __syncthreads();   // previous tile's compute done before overwrite
        As[lk + 0][lr] = av.x; As[lk + 1][lr] = av.y;
        As[lk + 2][lr] = av.z; As[lk + 3][lr] = av.w;
        Bs[lk + 0][lr] = bv.x; Bs[lk + 1][lr] = bv.y;
        Bs[lk + 2][lr] = bv.z; Bs[lk + 3][lr] = bv.w;
        __syncthreads();

#pragma unroll
        for (int k = 0; k < 8; k++) {
            float a[8], b[8];
            *(float4*)&a[0] = *(const float4*)&As[k][ty * 8];
            *(float4*)&a[4] = *(const float4*)&As[k][ty * 8 + 4];
            *(float4*)&b[0] = *(const float4*)&Bs[k][tx * 8];
            *(float4*)&b[4] = *(const float4*)&Bs[k][tx * 8 + 4];
#pragma unroll
            for (int i = 0; i < 8; i++)
#pragma unroll
                for (int j = 0; j < 8; j++)
                    acc[i][j] = fmaf(a[i], b[j], acc[i][j]);
        }
    }

#pragma unroll
    for (int i = 0; i < 8; i++) {
        const size_t m = m0 + ty * 8 + i;
#pragma unroll
        for (int j = 0; j < 8; j += 4) {
            const int n = n0 + tx * 8 + j;
            float4 o;
            o.x = acc[i][j + 0]; o.y = acc[i][j + 1];
            o.z = acc[i][j + 2]; o.w = acc[i][j + 3];
            if (bias) {
                o.x += bias[n + 0]; o.y += bias[n + 1];
                o.z += bias[n + 2]; o.w += bias[n + 3];
            }
            *(float4*)&C[m * N + n] = o;
        }
    }
}

// ---------------------------------------------------------------------------
// Flash attention (fp32, online softmax).
// Grid: (S/64, H, B). Block: 256 threads (16x16), 4x4 micro-tiles.
// Smem (dynamic, 69632 B):
//   Qs[d][q]  [64][68]   (Q^T, pre-scaled by 1/8)
//   Ks[d][k]  [64][68]   (K^T)
//   Vs[k][d]  [64][68]
//   Ps[k][q]  [64][68]   (probs, transposed)
// ---------------------------------------------------------------------------
__global__ void __launch_bounds__(256, 3)
flash_attn_kernel(const float* __restrict__ Q, const float* __restrict__ Kg,
                  const float* __restrict__ Vg, float* __restrict__ O)
{
    extern __shared__ float sm[];
    float (*Qs)[68] = (float(*)[68])(sm);
    float (*Ks)[68] = (float(*)[68])(sm + 64 * 68);
    float (*Vs)[68] = (float(*)[68])(sm + 2 * 64 * 68);
    float (*Ps)[68] = (float(*)[68])(sm + 3 * 64 * 68);

    const int tid = threadIdx.x;
    const int tx  = tid & 15;
    const int ty  = tid >> 4;
    const int q0  = blockIdx.x * 64;
    const int h   = blockIdx.y;
    const int b   = blockIdx.z;
    const size_t base = (size_t)b * SS * EMBED + (size_t)h * HDIM;

    // Load Q tile, transposed, scaled by 1/sqrt(64)=0.125
#pragma unroll
    for (int it = 0; it < 4; it++) {
        const int s  = tid + it * 256;   // 0..1023 float4 slots
        const int r  = s >> 4;           // query row 0..63
        const int d4 = (s & 15) * 4;     // dim 0..60
        float4 v = *(const float4*)&Q[base + (size_t)(q0 + r) * EMBED + d4];
        Qs[d4 + 0][r] = v.x * 0.125f; Qs[d4 + 1][r] = v.y * 0.125f;
        Qs[d4 + 2][r] = v.z * 0.125f; Qs[d4 + 3][r] = v.w * 0.125f;
    }

    float m_i[4], l_i[4], o[4][4];
#pragma unroll
    for (int i = 0; i < 4; i++) {
        m_i[i] = -INFINITY; l_i[i] = 0.f;
#pragma unroll
        for (int j = 0; j < 4; j++) o[i][j] = 0.f;
    }
    __syncthreads();

    for (int t = 0; t < SS / 64; t++) {
        // Load K (transposed) + V tiles
#pragma unroll
        for (int it = 0; it < 4; it++) {
            const int s  = tid + it * 256;
            const int r  = s >> 4;
            const int d4 = (s & 15) * 4;
            const size_t g = base + (size_t)(t * 64 + r) * EMBED + d4;
            float4 kv = *(const float4*)&Kg[g];
            Ks[d4 + 0][r] = kv.x; Ks[d4 + 1][r] = kv.y;
            Ks[d4 + 2][r] = kv.z; Ks[d4 + 3][r] = kv.w;
            float4 vv = *(const float4*)&Vg[g];
            *(float4*)&Vs[r][d4] = vv;
        }
        __syncthreads();

        // S tile: sacc[i][j] = sum_d Qs[d][ty*4+i] * Ks[d][tx*4+j]
        float sacc[4][4];
#pragma unroll
        for (int i = 0; i < 4; i++)
#pragma unroll
            for (int j = 0; j < 4; j++) sacc[i][j] = 0.f;

#pragma unroll
        for (int d = 0; d < 64; d++) {
            float4 qa = *(const float4*)&Qs[d][ty * 4];
            float4 kb = *(const float4*)&Ks[d][tx * 4];
            const float qv[4] = {qa.x, qa.y, qa.z, qa.w};
            const float kv[4] = {kb.x, kb.y, kb.z, kb.w};
#pragma unroll
            for (int i = 0; i < 4; i++)
#pragma unroll
                for (int j = 0; j < 4; j++)
                    sacc[i][j] = fmaf(qv[i], kv[j], sacc[i][j]);
        }

        // Online softmax (rows owned by same-ty threads; reduce across tx)
#pragma unroll
        for (int i = 0; i < 4; i++) {
            float mx = fmaxf(fmaxf(sacc[i][0], sacc[i][1]),
                             fmaxf(sacc[i][2], sacc[i][3]));
#pragma unroll
            for (int off = 1; off < 16; off <<= 1)
                mx = fmaxf(mx, __shfl_xor_sync(0xffffffffu, mx, off));
            const float m_new = fmaxf(m_i[i], mx);
            const float alpha = __expf(m_i[i] - m_new);   // exp(-inf)=0 first tile
            m_i[i] = m_new;

            float rs = 0.f;
#pragma unroll
            for (int j = 0; j < 4; j++) {
                const float p = __expf(sacc[i][j] - m_new);
                sacc[i][j] = p;
                rs += p;
            }
#pragma unroll
            for (int off = 1; off < 16; off <<= 1)
                rs += __shfl_xor_sync(0xffffffffu, rs, off);
            l_i[i] = l_i[i] * alpha + rs;

#pragma unroll
            for (int j = 0; j < 4; j++) {
                o[i][j] *= alpha;
                Ps[tx * 4 + j][ty * 4 + i] = sacc[i][j];  // transposed store
            }
        }
        __syncthreads();

        // PV: o[i][j] += sum_k Ps[k][ty*4+i] * Vs[k][tx*4+j]
#pragma unroll
        for (int k = 0; k < 64; k++) {
            float4 pa = *(const float4*)&Ps[k][ty * 4];
            float4 vb = *(const float4*)&Vs[k][tx * 4];
            const float pv[4] = {pa.x, pa.y, pa.z, pa.w};
            const float vv[4] = {vb.x, vb.y, vb.z, vb.w};
#pragma unroll
            for (int i = 0; i < 4; i++)
#pragma unroll
                for (int j = 0; j < 4; j++)
                    o[i][j] = fmaf(pv[i], vv[j], o[i][j]);
        }
        __syncthreads();
    }

    // Epilogue: normalize and write [b, s, h, d]
#pragma unroll
    for (int i = 0; i < 4; i++) {
        const float inv = 1.f / l_i[i];
        float4 ov;
        ov.x = o[i][0] * inv; ov.y = o[i][1] * inv;
        ov.z = o[i][2] * inv; ov.w = o[i][3] * inv;
        *(float4*)&O[base + (size_t)(q0 + ty * 4 + i) * EMBED + tx * 4] = ov;
    }
}

// ---------------------------------------------------------------------------
extern "C" void kernel_launch(void* const* d_in, const int* in_sizes, int n_in,
                              void* d_out, int out_size)
{
    const float* xq = (const float*)d_in[0];
    const float* xk = (const float*)d_in[1];
    const float* xv = (const float*)d_in[2];
    const float* Wq = (const float*)d_in[3];
    const float* Wk = (const float*)d_in[4];
    const float* Wv = (const float*)d_in[5];
    const float* Wo = (const float*)d_in[6];
    const float* bo = (const float*)d_in[7];
    float* out = (float*)d_out;

    float *q, *k, *v, *ao;
    cudaGetSymbolAddress((void**)&q,  g_q);
    cudaGetSymbolAddress((void**)&k,  g_k);
    cudaGetSymbolAddress((void**)&v,  g_v);
    cudaGetSymbolAddress((void**)&ao, g_ao);

    const dim3 gGrid(EMBED / 128, MTOT / 128);   // (8, 32)
    gemm_nt_kernel<<<gGrid, 256>>>(xq, Wq, nullptr, q, MTOT, EMBED, EMBED);
    gemm_nt_kernel<<<gGrid, 256>>>(xk, Wk, nullptr, k, MTOT, EMBED, EMBED);
    gemm_nt_kernel<<<gGrid, 256>>>(xv, Wv, nullptr, v, MTOT, EMBED, EMBED);

    const int smem = 4 * 64 * 68 * sizeof(float);  // 69632 B
    cudaFuncSetAttribute(flash_attn_kernel,
                         cudaFuncAttributeMaxDynamicSharedMemorySize, smem);
    flash_attn_kernel<<<dim3(SS / 64, NHEAD, BB), 256, smem>>>(q, k, v, ao);

    gemm_nt_kernel<<<gGrid, 256>>>(ao, Wo, bo, out, MTOT, EMBED, EMBED);
}

// round 3
// speedup vs baseline: 2.2106x; 2.2106x over previous
#include <cuda_runtime.h>
#include <math.h>
#include <stdint.h>

#define EMBED 1024
#define NHEAD 16
#define HDIM  64
#define BB    2
#define SS    2048
#define MTOT  4096

// Scratch (allocation-free contract: __device__ globals)
__device__ float g_q [MTOT*EMBED];
__device__ float g_k [MTOT*EMBED];
__device__ float g_v [MTOT*EMBED];
__device__ float g_ao[MTOT*EMBED];

// ---------------------------------------------------------------------------
// tf32 helpers (mma.sync — baseline PTX, works on plain sm_103 target)
// ---------------------------------------------------------------------------
__device__ __forceinline__ uint32_t f2tf32(float f) {
    uint32_t r;
    asm("cvt.rna.tf32.f32 %0, %1;" : "=r"(r) : "f"(f));
    return r;
}
__device__ __forceinline__ float tfbits(float f) {
    return __uint_as_float(f2tf32(f));
}
__device__ __forceinline__ void mma8(float* c, const uint32_t* a, const uint32_t* b) {
    asm volatile(
        "mma.sync.aligned.m16n8k8.row.col.f32.tf32.tf32.f32 "
        "{%0,%1,%2,%3}, {%4,%5,%6,%7}, {%8,%9}, {%0,%1,%2,%3};"
        : "+f"(c[0]), "+f"(c[1]), "+f"(c[2]), "+f"(c[3])
        : "r"(a[0]), "r"(a[1]), "r"(a[2]), "r"(a[3]), "r"(b[0]), "r"(b[1]));
}
#define FU(x) __float_as_uint(x)

// ===========================================================================
// tf32 mma GEMM (NT): C[M,1024] = A[M,1024] * B[1024,1024]^T (+bias)
// Tile 128x128, BK=32, 256 threads, 8 warps = 2m x 4n, warp = 64x32.
// Smem: As[2][32][136], Bs[2][32][136] floats (k-major, conflict-free frags)
// ===========================================================================
#define GEMM_SMEM (4 * 32 * 136 * 4)   // 69632 B

__global__ void __launch_bounds__(256)
gemm_mma(const float* __restrict__ A, const float* __restrict__ B,
         const float* __restrict__ bias, float* __restrict__ C)
{
    extern __shared__ float sm[];
    float* As = sm;            // 2 x 4352 floats
    float* Bs = sm + 8704;     // 2 x 4352 floats

    const int tid  = threadIdx.x;
    const int lane = tid & 31, wid = tid >> 5;
    const int gid  = lane >> 2, tig = lane & 3;
    const int wm   = (wid & 1) * 64;
    const int wn   = (wid >> 1) * 32;
    const int m0   = blockIdx.y * 128;
    const int n0   = blockIdx.x * 128;
    const int lrow = tid & 127;
    const int kq0  = tid >> 7;          // 0 or 1

    const float* Ag = A + (size_t)(m0 + lrow) * EMBED;
    const float* Bg = B + (size_t)(n0 + lrow) * EMBED;

    float acc[4][4][4];
#pragma unroll
    for (int mt = 0; mt < 4; mt++)
#pragma unroll
        for (int nt = 0; nt < 4; nt++)
#pragma unroll
            for (int r = 0; r < 4; r++) acc[mt][nt][r] = 0.f;

    float4 av[4], bv[4];
    // prologue: chunk 0 -> buf 0
#pragma unroll
    for (int it = 0; it < 4; it++) {
        const int kc = (kq0 + 2 * it) * 4;
        av[it] = *(const float4*)(Ag + kc);
        bv[it] = *(const float4*)(Bg + kc);
    }
#pragma unroll
    for (int it = 0; it < 4; it++) {
        const int kc = (kq0 + 2 * it) * 4;
        As[(kc + 0) * 136 + lrow] = tfbits(av[it].x);
        As[(kc + 1) * 136 + lrow] = tfbits(av[it].y);
        As[(kc + 2) * 136 + lrow] = tfbits(av[it].z);
        As[(kc + 3) * 136 + lrow] = tfbits(av[it].w);
        Bs[(kc + 0) * 136 + lrow] = tfbits(bv[it].x);
        Bs[(kc + 1) * 136 + lrow] = tfbits(bv[it].y);
        Bs[(kc + 2) * 136 + lrow] = tfbits(bv[it].z);
        Bs[(kc + 3) * 136 + lrow] = tfbits(bv[it].w);
    }
    __syncthreads();

    for (int kt = 0; kt < 32; kt++) {
        const int buf = kt & 1;
        if (kt < 31) {
#pragma unroll
            for (int it = 0; it < 4; it++) {
                const int kc = (kt + 1) * 32 + (kq0 + 2 * it) * 4;
                av[it] = *(const float4*)(Ag + kc);
                bv[it] = *(const float4*)(Bg + kc);
            }
        }
        const float* Ab = As + buf * 4352;
        const float* Bb = Bs + buf * 4352;
#pragma unroll
        for (int ks = 0; ks < 4; ks++) {
            const int kb = (ks * 8 + tig) * 136;
            uint32_t af[4][4];
#pragma unroll
            for (int mt = 0; mt < 4; mt++) {
                const float* p = Ab + kb + wm + mt * 16 + gid;
                af[mt][0] = FU(p[0]);
                af[mt][1] = FU(p[8]);
                af[mt][2] = FU(p[4 * 136]);
                af[mt][3] = FU(p[4 * 136 + 8]);
            }
#pragma unroll
            for (int nt = 0; nt < 4; nt++) {
                const float* q = Bb + kb + wn + nt * 8 + gid;
                uint32_t bf[2] = { FU(q[0]), FU(q[4 * 136]) };
#pragma unroll
                for (int mt = 0; mt < 4; mt++) mma8(acc[mt][nt], af[mt], bf);
            }
        }
        if (kt < 31) {
            float* Ad = As + (buf ^ 1) * 4352;
            float* Bd = Bs + (buf ^ 1) * 4352;
#pragma unroll
            for (int it = 0; it < 4; it++) {
                const int kc = (kq0 + 2 * it) * 4;
                Ad[(kc + 0) * 136 + lrow] = tfbits(av[it].x);
                Ad[(kc + 1) * 136 + lrow] = tfbits(av[it].y);
                Ad[(kc + 2) * 136 + lrow] = tfbits(av[it].z);
                Ad[(kc + 3) * 136 + lrow] = tfbits(av[it].w);
                Bd[(kc + 0) * 136 + lrow] = tfbits(bv[it].x);
                Bd[(kc + 1) * 136 + lrow] = tfbits(bv[it].y);
                Bd[(kc + 2) * 136 + lrow] = tfbits(bv[it].z);
                Bd[(kc + 3) * 136 + lrow] = tfbits(bv[it].w);
            }
        }
        __syncthreads();
    }

    // epilogue
#pragma unroll
    for (int mt = 0; mt < 4; mt++) {
        const int r = m0 + wm + mt * 16 + gid;
#pragma unroll
        for (int nt = 0; nt < 4; nt++) {
            const int c = n0 + wn + nt * 8 + 2 * tig;
            float b0 = 0.f, b1 = 0.f;
            if (bias) { b0 = bias[c]; b1 = bias[c + 1]; }
            float2 v0 = { acc[mt][nt][0] + b0, acc[mt][nt][1] + b1 };
            float2 v1 = { acc[mt][nt][2] + b0, acc[mt][nt][3] + b1 };
            *(float2*)&C[(size_t)r * EMBED + c]       = v0;
            *(float2*)&C[(size_t)(r + 8) * EMBED + c] = v1;
        }
    }
}

// ===========================================================================
// Flash attention with tf32 mma.
// CTA: 128 q rows x full kv sweep (tiles of 128). 256 threads, 8 warps.
// Warp w owns q rows [w*16, w*16+16) -> complete rows, warp-local softmax.
// Smem floats: Qs[128][68], Ks[128][68], Vt[64][132], Ps[128][132]
// ===========================================================================
#define FLASH_SMEM (42752 * 4)   // 171008 B

__global__ void __launch_bounds__(256)
flash_mma(const float* __restrict__ Q, const float* __restrict__ K,
          const float* __restrict__ V, float* __restrict__ O)
{
    extern __shared__ float sm[];
    float* Qs = sm;              // [128][68]
    float* Ks = sm + 8704;       // [128][68]
    float* Vt = sm + 17408;      // [64][132]  (V transposed: Vt[d][kv])
    float* Ps = sm + 25856;      // [128][132]

    const int tid  = threadIdx.x;
    const int lane = tid & 31, w = tid >> 5;
    const int gid  = lane >> 2, tig = lane & 3;
    const int q0   = blockIdx.x * 128;
    const size_t base = (size_t)blockIdx.z * SS * EMBED + (size_t)blockIdx.y * HDIM;

    // Load Q tile (coalesced), scale by 1/8, tf32-quantize
#pragma unroll
    for (int it = 0; it < 8; it++) {
        const int s = tid + it * 256;
        const int row = s >> 4, d4 = (s & 15) * 4;
        float4 v = *(const float4*)&Q[base + (size_t)(q0 + row) * EMBED + d4];
        float4 u;
        u.x = tfbits(v.x * 0.125f); u.y = tfbits(v.y * 0.125f);
        u.z = tfbits(v.z * 0.125f); u.w = tfbits(v.w * 0.125f);
        *(float4*)&Qs[row * 68 + d4] = u;
    }

    float o[8][4];
#pragma unroll
    for (int nt = 0; nt < 8; nt++)
#pragma unroll
        for (int r = 0; r < 4; r++) o[nt][r] = 0.f;
    float m0r = -1e30f, m1r = -1e30f, l0 = 0.f, l1 = 0.f;

    const int prow0 = (w * 16 + gid) * 132;
    const int prow1 = prow0 + 8 * 132;

    for (int t = 0; t < SS / 128; t++) {
        // K tile (coalesced, tf32)
#pragma unroll
        for (int it = 0; it < 8; it++) {
            const int s = tid + it * 256;
            const int row = s >> 4, d4 = (s & 15) * 4;
            float4 v = *(const float4*)&K[base + (size_t)(t * 128 + row) * EMBED + d4];
            float4 u;
            u.x = tfbits(v.x); u.y = tfbits(v.y);
            u.z = tfbits(v.z); u.w = tfbits(v.w);
            *(float4*)&Ks[row * 68 + d4] = u;
        }
        // V tile transposed into Vt[d][kv] (conflict-free column stores)
        {
            const int kvrow = tid & 127;
            const int dq0 = tid >> 7;
#pragma unroll
            for (int it = 0; it < 8; it++) {
                const int d4 = (dq0 + 2 * it) * 4;
                float4 v = *(const float4*)&V[base + (size_t)(t * 128 + kvrow) * EMBED + d4];
                Vt[(d4 + 0) * 132 + kvrow] = tfbits(v.x);
                Vt[(d4 + 1) * 132 + kvrow] = tfbits(v.y);
                Vt[(d4 + 2) * 132 + kvrow] = tfbits(v.z);
                Vt[(d4 + 3) * 132 + kvrow] = tfbits(v.w);
            }
        }
        __syncthreads();

        // S = Q K^T : warp w computes rows w*16..+16, all 128 kv cols
        float sacc[16][4];
#pragma unroll
        for (int nt = 0; nt < 16; nt++)
#pragma unroll
            for (int r = 0; r < 4; r++) sacc[nt][r] = 0.f;

#pragma unroll
        for (int ks = 0; ks < 8; ks++) {
            const float* ap = Qs + (w * 16 + gid) * 68 + ks * 8 + tig;
            uint32_t af[4] = { FU(ap[0]), FU(ap[8 * 68]), FU(ap[4]), FU(ap[8 * 68 + 4]) };
#pragma unroll
            for (int nt = 0; nt < 16; nt++) {
                const float* bp = Ks + (nt * 8 + gid) * 68 + ks * 8 + tig;
                uint32_t bf[2] = { FU(bp[0]), FU(bp[4]) };
                mma8(sacc[nt], af, bf);
            }
        }

        // Online softmax (rows live entirely in this warp; reduce over tig)
        float mx0 = -1e30f, mx1 = -1e30f;
#pragma unroll
        for (int nt = 0; nt < 16; nt++) {
            mx0 = fmaxf(mx0, fmaxf(sacc[nt][0], sacc[nt][1]));
            mx1 = fmaxf(mx1, fmaxf(sacc[nt][2], sacc[nt][3]));
        }
        mx0 = fmaxf(mx0, __shfl_xor_sync(0xffffffffu, mx0, 1));
        mx0 = fmaxf(mx0, __shfl_xor_sync(0xffffffffu, mx0, 2));
        mx1 = fmaxf(mx1, __shfl_xor_sync(0xffffffffu, mx1, 1));
        mx1 = fmaxf(mx1, __shfl_xor_sync(0xffffffffu, mx1, 2));

        const float mn0 = fmaxf(m0r, mx0), mn1 = fmaxf(m1r, mx1);
        const float al0 = __expf(m0r - mn0), al1 = __expf(m1r - mn1);
        m0r = mn0; m1r = mn1;

        float rs0 = 0.f, rs1 = 0.f;
#pragma unroll
        for (int nt = 0; nt < 16; nt++) {
            const float p0 = __expf(sacc[nt][0] - mn0);
            const float p1 = __expf(sacc[nt][1] - mn0);
            const float p2 = __expf(sacc[nt][2] - mn1);
            const float p3 = __expf(sacc[nt][3] - mn1);
            rs0 += p0 + p1; rs1 += p2 + p3;
            const int col = nt * 8 + 2 * tig;
            float2 t0 = { tfbits(p0), tfbits(p1) };
            float2 t1 = { tfbits(p2), tfbits(p3) };
            *(float2*)&Ps[prow0 + col] = t0;
            *(float2*)&Ps[prow1 + col] = t1;
        }
        rs0 += __shfl_xor_sync(0xffffffffu, rs0, 1);
        rs0 += __shfl_xor_sync(0xffffffffu, rs0, 2);
        rs1 += __shfl_xor_sync(0xffffffffu, rs1, 1);
        rs1 += __shfl_xor_sync(0xffffffffu, rs1, 2);
        l0 = l0 * al0 + rs0;
        l1 = l1 * al1 + rs1;

#pragma unroll
        for (int nt = 0; nt < 8; nt++) {
            o[nt][0] *= al0; o[nt][1] *= al0;
            o[nt][2] *= al1; o[nt][3] *= al1;
        }
        __syncwarp();

        // PV: O(128x64) += P(128x128) * V(128x64); B operand = Vt[d][kv]
#pragma unroll
        for (int ks = 0; ks < 16; ks++) {
            const float* ap = Ps + prow0 + ks * 8 + tig;
            uint32_t af[4] = { FU(ap[0]), FU(ap[8 * 132]), FU(ap[4]), FU(ap[8 * 132 + 4]) };
#pragma unroll
            for (int nt = 0; nt < 8; nt++) {
                const float* bp = Vt + (nt * 8 + gid) * 132 + ks * 8 + tig;
                uint32_t bf[2] = { FU(bp[0]), FU(bp[4]) };
                mma8(o[nt], af, bf);
            }
        }
        __syncthreads();
    }

    // epilogue: normalize, write [b, s, h, d]
    const float inv0 = 1.f / l0, inv1 = 1.f / l1;
    const int r0 = q0 + w * 16 + gid;
#pragma unroll
    for (int nt = 0; nt < 8; nt++) {
        const int d = nt * 8 + 2 * tig;
        float2 v0 = { o[nt][0] * inv0, o[nt][1] * inv0 };
        float2 v1 = { o[nt][2] * inv1, o[nt][3] * inv1 };
        *(float2*)&O[base + (size_t)r0 * EMBED + d]       = v0;
        *(float2*)&O[base + (size_t)(r0 + 8) * EMBED + d] = v1;
    }
}

// ---------------------------------------------------------------------------
extern "C" void kernel_launch(void* const* d_in, const int* in_sizes, int n_in,
                              void* d_out, int out_size)
{
    const float* xq = (const float*)d_in[0];
    const float* xk = (const float*)d_in[1];
    const float* xv = (const float*)d_in[2];
    const float* Wq = (const float*)d_in[3];
    const float* Wk = (const float*)d_in[4];
    const float* Wv = (const float*)d_in[5];
    const float* Wo = (const float*)d_in[6];
    const float* bo = (const float*)d_in[7];
    float* out = (float*)d_out;

    float *q, *k, *v, *ao;
    cudaGetSymbolAddress((void**)&q,  g_q);
    cudaGetSymbolAddress((void**)&k,  g_k);
    cudaGetSymbolAddress((void**)&v,  g_v);
    cudaGetSymbolAddress((void**)&ao, g_ao);

    cudaFuncSetAttribute(gemm_mma,
                         cudaFuncAttributeMaxDynamicSharedMemorySize, GEMM_SMEM);
    cudaFuncSetAttribute(flash_mma,
                         cudaFuncAttributeMaxDynamicSharedMemorySize, FLASH_SMEM);

    const dim3 gGrid(EMBED / 128, MTOT / 128);   // (8, 32)
    gemm_mma<<<gGrid, 256, GEMM_SMEM>>>(xq, Wq, nullptr, q);
    gemm_mma<<<gGrid, 256, GEMM_SMEM>>>(xk, Wk, nullptr, k);
    gemm_mma<<<gGrid, 256, GEMM_SMEM>>>(xv, Wv, nullptr, v);

    flash_mma<<<dim3(SS / 128, NHEAD, BB), 256, FLASH_SMEM>>>(q, k, v, ao);

    gemm_mma<<<gGrid, 256, GEMM_SMEM>>>(ao, Wo, bo, out);
}

// round 4
// speedup vs baseline: 2.4806x; 1.1221x over previous
#include <cuda_runtime.h>
#include <math.h>
#include <stdint.h>

#define EMBED 1024
#define NHEAD 16
#define HDIM  64
#define BB    2
#define SS    2048
#define MTOT  4096

// Scratch (allocation-free contract: __device__ globals)
__device__ float g_q [MTOT*EMBED];
__device__ float g_k [MTOT*EMBED];
__device__ float g_v [MTOT*EMBED];
__device__ float g_ao[MTOT*EMBED];

// ---------------------------------------------------------------------------
// helpers
// ---------------------------------------------------------------------------
__device__ __forceinline__ uint32_t f2tf32(float f) {
    uint32_t r;
    asm("cvt.rna.tf32.f32 %0, %1;" : "=r"(r) : "f"(f));
    return r;
}
__device__ __forceinline__ float tfbits(float f) {
    return __uint_as_float(f2tf32(f));
}
__device__ __forceinline__ float ex2(float x) {
    float r;
    asm("ex2.approx.f32 %0, %1;" : "=f"(r) : "f"(x));
    return r;
}
__device__ __forceinline__ void mma8(float* c, const uint32_t* a, const uint32_t* b) {
    asm volatile(
        "mma.sync.aligned.m16n8k8.row.col.f32.tf32.tf32.f32 "
        "{%0,%1,%2,%3}, {%4,%5,%6,%7}, {%8,%9}, {%0,%1,%2,%3};"
        : "+f"(c[0]), "+f"(c[1]), "+f"(c[2]), "+f"(c[3])
        : "r"(a[0]), "r"(a[1]), "r"(a[2]), "r"(a[3]), "r"(b[0]), "r"(b[1]));
}
#define FU(x) __float_as_uint(x)

// ===========================================================================
// tf32 mma GEMM (NT): C[M,1024] = A[M,1024]*B[1024,1024]^T (+bias)
// Tile 128x128, BK=16, 256 thr, 8 warps = 2m x 4n (warp 64x32).
// As k-major with m-pair permutation (m, m+8 adjacent -> 64-bit frag loads).
// 2 CTAs/SM (static smem 34.8KB, <=128 regs).
// ===========================================================================
__global__ void __launch_bounds__(256, 2)
gemm_mma(const float* __restrict__ A, const float* __restrict__ B,
         const float* __restrict__ bias, float* __restrict__ C)
{
    __shared__ float As[2][16 * 136];
    __shared__ float Bs[2][16 * 136];

    const int tid  = threadIdx.x;
    const int lane = tid & 31;
    const int wid  = tid >> 5;
    const int gid  = lane >> 2, tig = lane & 3;
    const int wm   = (wid & 1) * 64;
    const int wn   = (wid >> 1) * 32;
    const int m0   = blockIdx.y * 128;
    const int n0   = blockIdx.x * 128;
    const int lrow = tid & 127;
    const int kh   = (tid >> 7) * 8;            // k half: 0 or 8
    const int posm = (lrow & ~15) | ((lrow & 7) << 1) | ((lrow >> 3) & 1);

    const float* Ag = A + (size_t)(m0 + lrow) * EMBED + kh;
    const float* Bg = B + (size_t)(n0 + lrow) * EMBED + kh;

    float acc[4][4][4];
#pragma unroll
    for (int mt = 0; mt < 4; mt++)
#pragma unroll
        for (int nt = 0; nt < 4; nt++)
#pragma unroll
            for (int r = 0; r < 4; r++) acc[mt][nt][r] = 0.f;

    float4 a0v, a1v, b0v, b1v;
    a0v = *(const float4*)(Ag);     a1v = *(const float4*)(Ag + 4);
    b0v = *(const float4*)(Bg);     b1v = *(const float4*)(Bg + 4);
    {   // stage chunk 0 -> buf 0
        float* Ad = As[0]; float* Bd = Bs[0];
        const float aa[8] = {a0v.x,a0v.y,a0v.z,a0v.w,a1v.x,a1v.y,a1v.z,a1v.w};
        const float bb[8] = {b0v.x,b0v.y,b0v.z,b0v.w,b1v.x,b1v.y,b1v.z,b1v.w};
#pragma unroll
        for (int j = 0; j < 8; j++) {
            Ad[(kh + j) * 136 + posm] = tfbits(aa[j]);
            Bd[(kh + j) * 136 + lrow] = tfbits(bb[j]);
        }
    }
    __syncthreads();

    for (int kt = 0; kt < 64; kt++) {
        const int buf = kt & 1;
        if (kt < 63) {
            a0v = *(const float4*)(Ag + (kt + 1) * 16);
            a1v = *(const float4*)(Ag + (kt + 1) * 16 + 4);
            b0v = *(const float4*)(Bg + (kt + 1) * 16);
            b1v = *(const float4*)(Bg + (kt + 1) * 16 + 4);
        }
#pragma unroll
        for (int ks = 0; ks < 2; ks++) {
            const float* Ab = As[buf] + (ks * 8 + tig) * 136;
            const float* Bb = Bs[buf] + (ks * 8 + tig) * 136;
            uint32_t af[4][4];
#pragma unroll
            for (int mt = 0; mt < 4; mt++) {
                float2 lo = *(const float2*)&Ab[wm + mt * 16 + 2 * gid];
                float2 hi = *(const float2*)&Ab[544 + wm + mt * 16 + 2 * gid];
                af[mt][0] = FU(lo.x); af[mt][1] = FU(lo.y);
                af[mt][2] = FU(hi.x); af[mt][3] = FU(hi.y);
            }
#pragma unroll
            for (int nt = 0; nt < 4; nt++) {
                uint32_t bf[2] = { FU(Bb[wn + nt * 8 + gid]),
                                   FU(Bb[544 + wn + nt * 8 + gid]) };
#pragma unroll
                for (int mt = 0; mt < 4; mt++) mma8(acc[mt][nt], af[mt], bf);
            }
        }
        if (kt < 63) {
            float* Ad = As[buf ^ 1]; float* Bd = Bs[buf ^ 1];
            const float aa[8] = {a0v.x,a0v.y,a0v.z,a0v.w,a1v.x,a1v.y,a1v.z,a1v.w};
            const float bb[8] = {b0v.x,b0v.y,b0v.z,b0v.w,b1v.x,b1v.y,b1v.z,b1v.w};
#pragma unroll
            for (int j = 0; j < 8; j++) {
                Ad[(kh + j) * 136 + posm] = tfbits(aa[j]);
                Bd[(kh + j) * 136 + lrow] = tfbits(bb[j]);
            }
        }
        __syncthreads();
    }

    // epilogue
#pragma unroll
    for (int mt = 0; mt < 4; mt++) {
        const int r = m0 + wm + mt * 16 + gid;
#pragma unroll
        for (int nt = 0; nt < 4; nt++) {
            const int c = n0 + wn + nt * 8 + 2 * tig;
            float bq0 = 0.f, bq1 = 0.f;
            if (bias) { bq0 = bias[c]; bq1 = bias[c + 1]; }
            float2 v0 = { acc[mt][nt][0] + bq0, acc[mt][nt][1] + bq1 };
            float2 v1 = { acc[mt][nt][2] + bq0, acc[mt][nt][3] + bq1 };
            *(float2*)&C[(size_t)r * EMBED + c]       = v0;
            *(float2*)&C[(size_t)(r + 8) * EMBED + c] = v1;
        }
    }
}

// ===========================================================================
// Flash attention, tf32 mma, register-resident Q and P.
// CTA: 128 q rows, kv tiles of 64. 256 thr / 8 warps; warp owns 16 q rows.
// Smem: Ks[64][72] (pair-permuted d), Vt[64 d][72] (transposed, pair-perm kv)
// P: S-accums -> PV A-frags via warp shuffles (no smem, no extra barrier).
// ===========================================================================
#define LOG2E 1.4426950408889634f
#define QSCALE (0.125f * LOG2E)

__global__ void __launch_bounds__(256, 2)
flash_mma(const float* __restrict__ Q, const float* __restrict__ K,
          const float* __restrict__ V, float* __restrict__ O)
{
    __shared__ float Ks[64 * 72];
    __shared__ float Vt[4640];

    const int tid  = threadIdx.x;
    const int lane = tid & 31, w = tid >> 5;
    const int gid  = lane >> 2, tig = lane & 3;
    const int q0   = blockIdx.x * 128;
    const size_t base = (size_t)blockIdx.z * SS * EMBED + (size_t)blockIdx.y * HDIM;

    // Q fragments in registers (16 rows x 64 d per warp), pre-scaled
    uint32_t qf[8][4];
    {
        const float* Qw = Q + base + (size_t)(q0 + w * 16 + gid) * EMBED;
#pragma unroll
        for (int ks = 0; ks < 8; ks++) {
            const int c = ks * 8 + tig;
            qf[ks][0] = f2tf32(Qw[c] * QSCALE);
            qf[ks][1] = f2tf32(Qw[8 * EMBED + c] * QSCALE);
            qf[ks][2] = f2tf32(Qw[c + 4] * QSCALE);
            qf[ks][3] = f2tf32(Qw[8 * EMBED + c + 4] * QSCALE);
        }
    }

    float o[8][4];
#pragma unroll
    for (int dt = 0; dt < 8; dt++)
#pragma unroll
        for (int r = 0; r < 4; r++) o[dt][r] = 0.f;
    float mr0 = -1e30f, mr1 = -1e30f, l0 = 0.f, l1 = 0.f;

    // staging map: srow = kv row (K) / kv row (V); dseg = 16-d segment
    const int srow = tid >> 2;
    const int dseg = (tid & 3) * 16;
    const int pvkv = (srow & 56) | ((srow & 3) << 1) | ((srow >> 2) & 1);
    const int src0 = (lane & ~3) | (tig >> 1);
    const int src1 = src0 + 2;

    for (int t = 0; t < SS / 64; t++) {
        // ---- stage K (pair-permuted d) and V (transposed, pair-perm kv) ----
        const float* Kp = K + base + (size_t)(t * 64 + srow) * EMBED + dseg;
        const float* Vp = V + base + (size_t)(t * 64 + srow) * EMBED + dseg;
        float4 k0 = *(const float4*)(Kp);     float4 k1 = *(const float4*)(Kp + 4);
        float4 k2 = *(const float4*)(Kp + 8); float4 k3 = *(const float4*)(Kp + 12);
        float4 v0 = *(const float4*)(Vp);     float4 v1 = *(const float4*)(Vp + 4);
        float4 v2 = *(const float4*)(Vp + 8); float4 v3 = *(const float4*)(Vp + 12);
        __syncthreads();   // previous tile fully consumed
        {
            float* kr = Ks + srow * 72 + dseg;
            const float ka[8] = {k0.x,k0.y,k0.z,k0.w,k1.x,k1.y,k1.z,k1.w};
            const float kb[8] = {k2.x,k2.y,k2.z,k2.w,k3.x,k3.y,k3.z,k3.w};
#pragma unroll
            for (int j = 0; j < 4; j++) {
                float2 p0 = { tfbits(ka[j]), tfbits(ka[j + 4]) };
                float2 p1 = { tfbits(kb[j]), tfbits(kb[j + 4]) };
                *(float2*)&kr[2 * j]     = p0;
                *(float2*)&kr[8 + 2 * j] = p1;
            }
            const float va[16] = {v0.x,v0.y,v0.z,v0.w,v1.x,v1.y,v1.z,v1.w,
                                  v2.x,v2.y,v2.z,v2.w,v3.x,v3.y,v3.z,v3.w};
#pragma unroll
            for (int j = 0; j < 16; j++) {
                const int d = dseg + j;
                Vt[d * 72 + ((d >> 4) << 3) + pvkv] = tfbits(va[j]);
            }
        }
        __syncthreads();

        // ---- S = Q K^T (16 q x 64 kv per warp) ----
        float sacc[8][4];
#pragma unroll
        for (int nt = 0; nt < 8; nt++)
#pragma unroll
            for (int r = 0; r < 4; r++) sacc[nt][r] = 0.f;
#pragma unroll
        for (int ks = 0; ks < 8; ks++) {
            const int kcol = ks * 8 + 2 * tig;
#pragma unroll
            for (int nt = 0; nt < 8; nt++) {
                float2 kf = *(const float2*)&Ks[(nt * 8 + gid) * 72 + kcol];
                uint32_t bf[2] = { FU(kf.x), FU(kf.y) };
                mma8(sacc[nt], qf[ks], bf);
            }
        }

        // ---- online softmax (exp2 domain), rows warp-local ----
        float mx0 = -1e30f, mx1 = -1e30f;
#pragma unroll
        for (int nt = 0; nt < 8; nt++) {
            mx0 = fmaxf(mx0, fmaxf(sacc[nt][0], sacc[nt][1]));
            mx1 = fmaxf(mx1, fmaxf(sacc[nt][2], sacc[nt][3]));
        }
        mx0 = fmaxf(mx0, __shfl_xor_sync(0xffffffffu, mx0, 1));
        mx0 = fmaxf(mx0, __shfl_xor_sync(0xffffffffu, mx0, 2));
        mx1 = fmaxf(mx1, __shfl_xor_sync(0xffffffffu, mx1, 1));
        mx1 = fmaxf(mx1, __shfl_xor_sync(0xffffffffu, mx1, 2));

        const float mn0 = fmaxf(mr0, mx0), mn1 = fmaxf(mr1, mx1);
        const float al0 = ex2(mr0 - mn0),  al1 = ex2(mr1 - mn1);
        mr0 = mn0; mr1 = mn1;
        l0 *= al0; l1 *= al1;
#pragma unroll
        for (int dt = 0; dt < 8; dt++) {
            o[dt][0] *= al0; o[dt][1] *= al0;
            o[dt][2] *= al1; o[dt][3] *= al1;
        }

        // ---- exp + P->A-frag shuffle + PV, fused per 8-kv block ----
        float rs0 = 0.f, rs1 = 0.f;
#pragma unroll
        for (int nt = 0; nt < 8; nt++) {
            const float p0 = tfbits(ex2(sacc[nt][0] - mn0));
            const float p1 = tfbits(ex2(sacc[nt][1] - mn0));
            const float p2 = tfbits(ex2(sacc[nt][2] - mn1));
            const float p3 = tfbits(ex2(sacc[nt][3] - mn1));
            rs0 += p0 + p1; rs1 += p2 + p3;

            uint32_t af[4];
            {
                const float e00 = __shfl_sync(0xffffffffu, p0, src0);
                const float e01 = __shfl_sync(0xffffffffu, p1, src0);
                af[0] = FU((tig & 1) ? e01 : e00);
                const float e10 = __shfl_sync(0xffffffffu, p2, src0);
                const float e11 = __shfl_sync(0xffffffffu, p3, src0);
                af[1] = FU((tig & 1) ? e11 : e10);
                const float e20 = __shfl_sync(0xffffffffu, p0, src1);
                const float e21 = __shfl_sync(0xffffffffu, p1, src1);
                af[2] = FU((tig & 1) ? e21 : e20);
                const float e30 = __shfl_sync(0xffffffffu, p2, src1);
                const float e31 = __shfl_sync(0xffffffffu, p3, src1);
                af[3] = FU((tig & 1) ? e31 : e30);
            }
            const int vcol = nt * 8 + 2 * tig;
#pragma unroll
            for (int dt = 0; dt < 8; dt++) {
                const int drow = dt * 8 + gid;
                float2 vf = *(const float2*)&Vt[drow * 72 + ((drow >> 4) << 3) + vcol];
                uint32_t bf[2] = { FU(vf.x), FU(vf.y) };
                mma8(o[dt], af, bf);
            }
        }
        rs0 += __shfl_xor_sync(0xffffffffu, rs0, 1);
        rs0 += __shfl_xor_sync(0xffffffffu, rs0, 2);
        rs1 += __shfl_xor_sync(0xffffffffu, rs1, 1);
        rs1 += __shfl_xor_sync(0xffffffffu, rs1, 2);
        l0 += rs0; l1 += rs1;
    }

    // ---- epilogue ----
    const float inv0 = 1.f / l0, inv1 = 1.f / l1;
    const int r0 = q0 + w * 16 + gid;
#pragma unroll
    for (int dt = 0; dt < 8; dt++) {
        const int d = dt * 8 + 2 * tig;
        float2 u0 = { o[dt][0] * inv0, o[dt][1] * inv0 };
        float2 u1 = { o[dt][2] * inv1, o[dt][3] * inv1 };
        *(float2*)&O[base + (size_t)r0 * EMBED + d]       = u0;
        *(float2*)&O[base + (size_t)(r0 + 8) * EMBED + d] = u1;
    }
}

// ---------------------------------------------------------------------------
extern "C" void kernel_launch(void* const* d_in, const int* in_sizes, int n_in,
                              void* d_out, int out_size)
{
    const float* xq = (const float*)d_in[0];
    const float* xk = (const float*)d_in[1];
    const float* xv = (const float*)d_in[2];
    const float* Wq = (const float*)d_in[3];
    const float* Wk = (const float*)d_in[4];
    const float* Wv = (const float*)d_in[5];
    const float* Wo = (const float*)d_in[6];
    const float* bo = (const float*)d_in[7];
    float* out = (float*)d_out;

    float *q, *k, *v, *ao;
    cudaGetSymbolAddress((void**)&q,  g_q);
    cudaGetSymbolAddress((void**)&k,  g_k);
    cudaGetSymbolAddress((void**)&v,  g_v);
    cudaGetSymbolAddress((void**)&ao, g_ao);

    const dim3 gGrid(EMBED / 128, MTOT / 128);   // (8, 32)
    gemm_mma<<<gGrid, 256>>>(xq, Wq, nullptr, q);
    gemm_mma<<<gGrid, 256>>>(xk, Wk, nullptr, k);
    gemm_mma<<<gGrid, 256>>>(xv, Wv, nullptr, v);

    flash_mma<<<dim3(SS / 128, NHEAD, BB), 256>>>(q, k, v, ao);

    gemm_mma<<<gGrid, 256>>>(ao, Wo, bo, out);
}